// round 5
// baseline (speedup 1.0000x reference)
#include <cuda_runtime.h>
#include <cuda_bf16.h>

#define N_EXPERTS 48
#define D_IN 163840            // 2*1280*8*8
#define D_OUT 2
#define BATCH 512
#define THREADS 256
#define G 8                    // samples per group (same expert)
#define MAXG (N_EXPERTS + BATCH / G)   // 112 groups worst case
#define NSPLIT 80              // D_IN split -> CHUNK floats per tile
#define CHUNK (D_IN / NSPLIT)  // 2048 floats
#define N4 (CHUNK / 4)         // 512 float4
#define ITERS (N4 / THREADS)   // 2
#define GRID_MAIN (148 * 4)    // persistent CTAs

// ---- scratch (device globals: no allocation allowed) ----
__device__ int   g_ngroups;
__device__ int   g_tick;
__device__ int   g_group_expert[MAXG];
__device__ int   g_group_samples[MAXG * G];      // -1 = padded slot
__device__ float g_partials[BATCH * NSPLIT * 2];
__device__ int   g_count[BATCH];                 // zero-init, self-resetting

// ---------------------------------------------------------------
// Prekernel: deterministic stable grouping of samples by expert.
// 1 CTA, 512 threads, ~1-2us.
// ---------------------------------------------------------------
__global__ __launch_bounds__(BATCH)
void prep_kernel(const int* __restrict__ t) {
    __shared__ int sh_e[BATCH];
    __shared__ int segcnt[N_EXPERTS][8];
    __shared__ int segbase[N_EXPERTS][8];
    __shared__ int cnt[N_EXPERTS];
    __shared__ int gb[N_EXPERTS];
    __shared__ int rnk[BATCH];
    const int tid = threadIdx.x;

    int e = t[tid] - 1;
    e = ((e % N_EXPERTS) + N_EXPERTS) % N_EXPERTS;
    sh_e[tid] = e;
    if (tid == 0) g_tick = 0;
    __syncthreads();

    // per-(expert, 64-sample segment) counts
    if (tid < N_EXPERTS * 8) {
        const int ex = tid >> 3, seg = tid & 7;
        int c = 0;
        for (int j = seg * 64; j < seg * 64 + 64; j++) c += (sh_e[j] == ex);
        segcnt[ex][seg] = c;
    }
    __syncthreads();
    if (tid < N_EXPERTS) {
        int r = 0;
        for (int s = 0; s < 8; s++) { segbase[tid][s] = r; r += segcnt[tid][s]; }
        cnt[tid] = r;
    }
    __syncthreads();
    if (tid == 0) {
        int gsum = 0;
        for (int e2 = 0; e2 < N_EXPERTS; e2++) {
            gb[e2] = gsum;
            gsum += (cnt[e2] + G - 1) / G;
        }
        g_ngroups = gsum;
    }
    // init group table to "empty"
    for (int i = tid; i < MAXG * G; i += BATCH) g_group_samples[i] = -1;
    __syncthreads();
    // stable ranks within expert
    if (tid < N_EXPERTS * 8) {
        const int ex = tid >> 3, seg = tid & 7;
        int r = segbase[ex][seg];
        for (int j = seg * 64; j < seg * 64 + 64; j++)
            if (sh_e[j] == ex) rnk[j] = r++;
    }
    __syncthreads();
    {
        const int r = rnk[tid], ee = sh_e[tid];
        const int grp = gb[ee] + r / G;
        g_group_samples[grp * G + (r % G)] = tid;
        if ((r % G) == 0) g_group_expert[grp] = ee;
    }
}

// ---------------------------------------------------------------
// Main: persistent grouped split-K GEMV.
// Tile = (group of <=8 same-expert samples, CHUNK of D_IN).
// ---------------------------------------------------------------
__global__ __launch_bounds__(THREADS, 4)
void moe_gemv_grouped(const float* __restrict__ x,
                      const float* __restrict__ W,
                      const float* __restrict__ bias,
                      float* __restrict__ out) {
    __shared__ int   s_tile;
    __shared__ float s_red[THREADS / 32][2 * G];
    const int tid  = threadIdx.x;
    const int warp = tid >> 5;
    const int lane = tid & 31;
    const int total = g_ngroups * NSPLIT;
    const float4* __restrict__ x4 = reinterpret_cast<const float4*>(x);

    for (;;) {
        __syncthreads();                        // protect s_tile / s_red reuse
        if (tid == 0) s_tile = atomicAdd(&g_tick, 1);
        __syncthreads();
        const int tile = s_tile;
        if (tile >= total) break;

        const int grp   = tile / NSPLIT;
        const int split = tile - grp * NSPLIT;
        const int e     = g_group_expert[grp];
        const int s0    = g_group_samples[grp * G + 0];

        int samp[G];
        unsigned valid = 0;
        #pragma unroll
        for (int k = 0; k < G; k++) {
            int s = g_group_samples[grp * G + k];
            if (s >= 0) valid |= (1u << k); else s = s0;
            samp[k] = s;
        }

        const int base = split * CHUNK;
        int xi[G];
        #pragma unroll
        for (int k = 0; k < G; k++)
            xi[k] = samp[k] * (D_IN / 4) + (base >> 2);

        const float4* __restrict__ w4 =
            reinterpret_cast<const float4*>(W + (size_t)e * D_IN * D_OUT
                                              + (size_t)base * D_OUT);

        float acc[2 * G];
        #pragma unroll
        for (int v = 0; v < 2 * G; v++) acc[v] = 0.0f;

        #pragma unroll
        for (int it = 0; it < ITERS; it++) {
            const int i = tid + it * THREADS;
            const float4 w0 = w4[2 * i];       // dims d..d+1 (both outputs)
            const float4 w1 = w4[2 * i + 1];   // dims d+2..d+3
            #pragma unroll
            for (int k = 0; k < G; k++) {
                const float4 xq = __ldcs(&x4[xi[k] + i]);
                acc[2 * k + 0] = fmaf(xq.x, w0.x, acc[2 * k + 0]);
                acc[2 * k + 1] = fmaf(xq.x, w0.y, acc[2 * k + 1]);
                acc[2 * k + 0] = fmaf(xq.y, w0.z, acc[2 * k + 0]);
                acc[2 * k + 1] = fmaf(xq.y, w0.w, acc[2 * k + 1]);
                acc[2 * k + 0] = fmaf(xq.z, w1.x, acc[2 * k + 0]);
                acc[2 * k + 1] = fmaf(xq.z, w1.y, acc[2 * k + 1]);
                acc[2 * k + 0] = fmaf(xq.w, w1.z, acc[2 * k + 0]);
                acc[2 * k + 1] = fmaf(xq.w, w1.w, acc[2 * k + 1]);
            }
        }

        // warp-level reduce all 16 accumulators (fixed shuffle tree)
        #pragma unroll
        for (int off = 16; off > 0; off >>= 1) {
            #pragma unroll
            for (int v = 0; v < 2 * G; v++)
                acc[v] += __shfl_down_sync(0xFFFFFFFFu, acc[v], off);
        }
        if (lane == 0) {
            #pragma unroll
            for (int v = 0; v < 2 * G; v++) s_red[warp][v] = acc[v];
        }
        __syncthreads();

        if (warp == 0 && lane < 2 * G) {
            float v = 0.0f;
            #pragma unroll
            for (int w = 0; w < THREADS / 32; w++) v += s_red[w][lane];
            const int k = lane >> 1, c = lane & 1;
            const int s = samp[k];
            const bool ok = (valid >> k) & 1u;
            if (ok)
                g_partials[(s * NSPLIT + split) * 2 + c] = v;
            __threadfence();
            if (ok && c == 0) {
                int old = atomicAdd(&g_count[s], 1);
                if (old == NSPLIT - 1) {
                    g_count[s] = 0;             // reset for next graph replay
                    __threadfence();
                    volatile const float* p = g_partials + (size_t)s * NSPLIT * 2;
                    float f0 = 0.0f, f1 = 0.0f;
                    #pragma unroll 4
                    for (int sp = 0; sp < NSPLIT; sp++) {
                        f0 += p[2 * sp + 0];
                        f1 += p[2 * sp + 1];
                    }
                    out[2 * s + 0] = f0 + bias[2 * e + 0];
                    out[2 * s + 1] = f1 + bias[2 * e + 1];
                }
            }
        }
    }
}

extern "C" void kernel_launch(void* const* d_in, const int* in_sizes, int n_in,
                              void* d_out, int out_size) {
    const float* x    = (const float*)d_in[0];  // [512, 2,1280,8,8] fp32
    const int*   t    = (const int*)d_in[1];    // [512] int32
    const float* W    = (const float*)d_in[2];  // [48, 163840, 2] fp32
    const float* bias = (const float*)d_in[3];  // [48, 2] fp32
    float* out = (float*)d_out;                 // [512, 2] fp32

    prep_kernel<<<1, BATCH>>>(t);
    moe_gemv_grouped<<<GRID_MAIN, THREADS>>>(x, W, bias, out);
}

// round 6
// speedup vs baseline: 1.2521x; 1.2521x over previous
#include <cuda_runtime.h>
#include <cuda_bf16.h>

#define N_EXPERTS 48
#define D_IN 163840            // 2*1280*8*8
#define D_OUT 2
#define BATCH 512
#define THREADS 256
#define G 2                    // samples per group (same expert)
#define MAXG ((BATCH + N_EXPERTS) / G)   // 280 groups worst case
#define NSPLIT 16              // D_IN split
#define CHUNK (D_IN / NSPLIT)  // 10240 floats
#define N4 (CHUNK / 4)         // 2560 float4
#define ITERS (N4 / THREADS)   // 10
#define GRID_MAIN (MAXG * NSPLIT)   // 4480 CTAs

// ---- scratch (device globals: no allocation allowed) ----
__device__ int   g_group_expert[MAXG];
__device__ int   g_group_samples[MAXG * G];      // -1 = empty slot
__device__ float g_partials[BATCH * NSPLIT * 2];
__device__ int   g_count[BATCH];                 // zero-init, self-resetting

// ---------------------------------------------------------------
// Prekernel: deterministic stable grouping of samples by expert.
// 1 CTA, 512 threads, ~1-2us.
// ---------------------------------------------------------------
__global__ __launch_bounds__(BATCH)
void prep_kernel(const int* __restrict__ t) {
    __shared__ int sh_e[BATCH];
    __shared__ int segcnt[N_EXPERTS][8];
    __shared__ int segbase[N_EXPERTS][8];
    __shared__ int cnt[N_EXPERTS];
    __shared__ int gb[N_EXPERTS];
    __shared__ int rnk[BATCH];
    const int tid = threadIdx.x;

    int e = t[tid] - 1;
    e = ((e % N_EXPERTS) + N_EXPERTS) % N_EXPERTS;
    sh_e[tid] = e;
    __syncthreads();

    // per-(expert, 64-sample segment) counts
    if (tid < N_EXPERTS * 8) {
        const int ex = tid >> 3, seg = tid & 7;
        int c = 0;
        for (int j = seg * 64; j < seg * 64 + 64; j++) c += (sh_e[j] == ex);
        segcnt[ex][seg] = c;
    }
    __syncthreads();
    if (tid < N_EXPERTS) {
        int r = 0;
        for (int s = 0; s < 8; s++) { segbase[tid][s] = r; r += segcnt[tid][s]; }
        cnt[tid] = r;
    }
    __syncthreads();
    if (tid == 0) {
        int gsum = 0;
        for (int e2 = 0; e2 < N_EXPERTS; e2++) {
            gb[e2] = gsum;
            gsum += (cnt[e2] + G - 1) / G;
        }
    }
    // init group table to "empty"
    for (int i = tid; i < MAXG * G; i += BATCH) g_group_samples[i] = -1;
    __syncthreads();
    // stable ranks within expert
    if (tid < N_EXPERTS * 8) {
        const int ex = tid >> 3, seg = tid & 7;
        int r = segbase[ex][seg];
        for (int j = seg * 64; j < seg * 64 + 64; j++)
            if (sh_e[j] == ex) rnk[j] = r++;
    }
    __syncthreads();
    {
        const int r = rnk[tid], ee = sh_e[tid];
        const int grp = gb[ee] + r / G;
        g_group_samples[grp * G + (r % G)] = tid;
        if ((r % G) == 0) g_group_expert[grp] = ee;
    }
}

// ---------------------------------------------------------------
// Main: grouped split-K GEMV. One CTA per (pair, split) tile.
// Per iter: 2 x-loads (DRAM stream) + 2 W-loads (L2 hit), 16 FMA.
// ---------------------------------------------------------------
__global__ __launch_bounds__(THREADS, 6)
void moe_gemv_g2(const float* __restrict__ x,
                 const float* __restrict__ W,
                 const float* __restrict__ bias,
                 float* __restrict__ out) {
    const int grp   = blockIdx.x >> 4;          // NSPLIT = 16
    const int split = blockIdx.x & (NSPLIT - 1);
    const int tid   = threadIdx.x;

    const int sA = g_group_samples[grp * G + 0];
    if (sA < 0) return;                         // empty group slot
    const int sB_raw = g_group_samples[grp * G + 1];
    const bool hasB = (sB_raw >= 0);
    const int sB = hasB ? sB_raw : sA;
    const int e  = g_group_expert[grp];

    const int base4 = split * N4;               // float4 offset in sample row
    const float4* __restrict__ x4 = reinterpret_cast<const float4*>(x);
    const float4* __restrict__ wv =
        reinterpret_cast<const float4*>(W + (size_t)e * D_IN * D_OUT) + 2 * base4;
    const int xiA = sA * (D_IN / 4) + base4;
    const int xiB = sB * (D_IN / 4) + base4;

    float a0 = 0.0f, a1 = 0.0f, b0 = 0.0f, b1 = 0.0f;

    #pragma unroll
    for (int k = 0; k < ITERS; k++) {
        const int i = tid + k * THREADS;
        const float4 xa = __ldcs(&x4[xiA + i]);
        const float4 xb = __ldcs(&x4[xiB + i]);
        const float4 w0 = wv[2 * i];       // dims d,d+1: {W[d,0],W[d,1],W[d+1,0],W[d+1,1]}
        const float4 w1 = wv[2 * i + 1];   // dims d+2,d+3
        a0 = fmaf(xa.x, w0.x, a0);  a1 = fmaf(xa.x, w0.y, a1);
        b0 = fmaf(xb.x, w0.x, b0);  b1 = fmaf(xb.x, w0.y, b1);
        a0 = fmaf(xa.y, w0.z, a0);  a1 = fmaf(xa.y, w0.w, a1);
        b0 = fmaf(xb.y, w0.z, b0);  b1 = fmaf(xb.y, w0.w, b1);
        a0 = fmaf(xa.z, w1.x, a0);  a1 = fmaf(xa.z, w1.y, a1);
        b0 = fmaf(xb.z, w1.x, b0);  b1 = fmaf(xb.z, w1.y, b1);
        a0 = fmaf(xa.w, w1.z, a0);  a1 = fmaf(xa.w, w1.w, a1);
        b0 = fmaf(xb.w, w1.z, b0);  b1 = fmaf(xb.w, w1.w, b1);
    }

    // Warp reduction of 4 accumulators
    #pragma unroll
    for (int off = 16; off > 0; off >>= 1) {
        a0 += __shfl_down_sync(0xFFFFFFFFu, a0, off);
        a1 += __shfl_down_sync(0xFFFFFFFFu, a1, off);
        b0 += __shfl_down_sync(0xFFFFFFFFu, b0, off);
        b1 += __shfl_down_sync(0xFFFFFFFFu, b1, off);
    }

    __shared__ float s_red[THREADS / 32][4];
    const int warp = tid >> 5;
    const int lane = tid & 31;
    if (lane == 0) {
        s_red[warp][0] = a0; s_red[warp][1] = a1;
        s_red[warp][2] = b0; s_red[warp][3] = b1;
    }
    __syncthreads();

    if (tid == 0) {
        float f[4] = {0.0f, 0.0f, 0.0f, 0.0f};
        #pragma unroll
        for (int w = 0; w < THREADS / 32; w++) {
            f[0] += s_red[w][0]; f[1] += s_red[w][1];
            f[2] += s_red[w][2]; f[3] += s_red[w][3];
        }
        // Publish partials (unique slots -> deterministic)
        g_partials[(sA * NSPLIT + split) * 2 + 0] = f[0];
        g_partials[(sA * NSPLIT + split) * 2 + 1] = f[1];
        if (hasB) {
            g_partials[(sB * NSPLIT + split) * 2 + 0] = f[2];
            g_partials[(sB * NSPLIT + split) * 2 + 1] = f[3];
        }
        __threadfence();

        // Ticket per sample; last arriver finishes (fixed-order sum).
        #pragma unroll
        for (int which = 0; which < 2; which++) {
            if (which == 1 && !hasB) break;
            const int s = (which == 0) ? sA : sB;
            int old = atomicAdd(&g_count[s], 1);
            if (old == NSPLIT - 1) {
                g_count[s] = 0;                 // reset for next graph replay
                __threadfence();
                volatile const float* p = g_partials + (size_t)s * NSPLIT * 2;
                float o0 = 0.0f, o1 = 0.0f;
                #pragma unroll 4
                for (int sp = 0; sp < NSPLIT; sp++) {
                    o0 += p[2 * sp + 0];
                    o1 += p[2 * sp + 1];
                }
                out[2 * s + 0] = o0 + bias[2 * e + 0];
                out[2 * s + 1] = o1 + bias[2 * e + 1];
            }
        }
    }
}

extern "C" void kernel_launch(void* const* d_in, const int* in_sizes, int n_in,
                              void* d_out, int out_size) {
    const float* x    = (const float*)d_in[0];  // [512, 2,1280,8,8] fp32
    const int*   t    = (const int*)d_in[1];    // [512] int32
    const float* W    = (const float*)d_in[2];  // [48, 163840, 2] fp32
    const float* bias = (const float*)d_in[3];  // [48, 2] fp32
    float* out = (float*)d_out;                 // [512, 2] fp32

    prep_kernel<<<1, BATCH>>>(t);
    moe_gemv_g2<<<GRID_MAIN, THREADS>>>(x, W, bias, out);
}